// round 11
// baseline (speedup 1.0000x reference)
#include <cuda_runtime.h>
#include <math_constants.h>

// Global spatial max-pool: [B=64, H=56, W=56, C=256] f32 NHWC -> [B=64, C=256].
//
// FINAL — the R7 configuration verbatim, the best of 10 measured variants
// (35.0 us kernel, 5.98 TB/s = 74.7% of spec, rel_err 0.0).
//
// Evidence (10 rounds): every well-formed config (grid 896-3584, block
// 128-512, occ 70-97%, MLP 2-28, any epilogue/wave/cache structure) lands
// at 5.8-6.0 TB/s -> ~75% of the 8 TB/s spec is this chip's effective
// read-stream ceiling for this pattern. Deviations that regressed:
// persistent loops w/ in-loop barriers (-34%), runtime-bounded load loops
// (-13%), unroll 7 front-batch (-3%). This kernel sits on the ceiling.
//
// Structure:
//   - grid = 64 batches x 28 splits = 1792 blocks, 256 threads
//     (32 channel-groups x 8 spatial phases); warp reads 1KB coalesced.
//   - LDG.E.256 (ld.global.nc.v8.f32) with L1::no_allocate.L2::evict_first:
//     zero-reuse stream, skip L1 allocation, evict-first in L2.
//   - compile-time trip count, immediate LDG offsets, unroll 4 (best
//     measured steady-state MLP without front-batch L1tex-queue spread).
//   - smem cross-phase reduce; fused final reduce via last-block-per-batch:
//     release fence before counter bump, acquire fence after observing it
//     (R6 proved the race is real: rel_err 3e-4 without the acquire).
//   - counters self-reset for CUDA-graph replay determinism; max is
//     order-independent so block scheduling never affects output.

#define B_DIM   64
#define HW      3136              // 56*56
#define C_DIM   256
#define SPLIT   28
#define SPAN    (HW / SPLIT)      // 112 spatial positions per block
#define PHASES  8
#define ITERS   (SPAN / PHASES)   // 14

__device__ float        g_partial[B_DIM * SPLIT * C_DIM];  // 1.75 MB scratch
__device__ unsigned int g_count[B_DIM];                    // zero-init, self-resetting

__global__ __launch_bounds__(256, 8)
void gmax_fused(const float* __restrict__ in, float* __restrict__ out) {
    const int blk   = blockIdx.x;            // 0..1791
    const int b     = blk / SPLIT;
    const int split = blk - b * SPLIT;
    const int t     = threadIdx.x;
    const int g     = t & 31;                // 8-channel group (32 bytes)
    const int p     = t >> 5;                // spatial phase 0..7

    const float* __restrict__ base =
        in + (((size_t)(b * HW + split * SPAN + p)) << 8) + (g << 3);

    float a0 = -CUDART_INF_F, a1 = -CUDART_INF_F, a2 = -CUDART_INF_F, a3 = -CUDART_INF_F;
    float a4 = -CUDART_INF_F, a5 = -CUDART_INF_F, a6 = -CUDART_INF_F, a7 = -CUDART_INF_F;

    #pragma unroll 4
    for (int i = 0; i < ITERS; ++i) {
        float v0, v1, v2, v3, v4, v5, v6, v7;
        asm volatile(
            "ld.global.nc.L1::no_allocate.L2::evict_first.v8.f32 "
            "{%0,%1,%2,%3,%4,%5,%6,%7}, [%8];"
            : "=f"(v0), "=f"(v1), "=f"(v2), "=f"(v3),
              "=f"(v4), "=f"(v5), "=f"(v6), "=f"(v7)
            : "l"(base + (size_t)i * (PHASES * C_DIM)));
        a0 = fmaxf(a0, v0);  a1 = fmaxf(a1, v1);
        a2 = fmaxf(a2, v2);  a3 = fmaxf(a3, v3);
        a4 = fmaxf(a4, v4);  a5 = fmaxf(a5, v5);
        a6 = fmaxf(a6, v6);  a7 = fmaxf(a7, v7);
    }

    // Cross-phase reduce through smem: sm[p*256 + c], conflict-free.
    __shared__ float sm[PHASES * C_DIM];
    float* my = sm + t * 8;  // == p*256 + g*8
    my[0] = a0; my[1] = a1; my[2] = a2; my[3] = a3;
    my[4] = a4; my[5] = a5; my[6] = a6; my[7] = a7;
    __syncthreads();

    // Thread t == channel c: reduce over 8 phases, write block partial.
    {
        float m = sm[t];
        #pragma unroll
        for (int ph = 1; ph < PHASES; ++ph)
            m = fmaxf(m, sm[ph * C_DIM + t]);
        g_partial[blk * C_DIM + t] = m;
    }

    // Release: make partial visible, then bump the batch counter.
    __threadfence();
    __shared__ bool amLast;
    if (t == 0) {
        unsigned int old = atomicAdd(&g_count[b], 1u);
        amLast = (old == SPLIT - 1);
    }
    __syncthreads();

    if (amLast) {
        // Acquire: order our reads of g_partial after the observed counter.
        __threadfence();
        const float* part = g_partial + b * SPLIT * C_DIM;
        float m = part[t];
        #pragma unroll
        for (int s = 1; s < SPLIT; ++s)
            m = fmaxf(m, part[s * C_DIM + t]);
        out[b * C_DIM + t] = m;
        if (t == 0) g_count[b] = 0;   // self-reset for next graph replay
    }
}

extern "C" void kernel_launch(void* const* d_in, const int* in_sizes, int n_in,
                              void* d_out, int out_size) {
    const float* in  = (const float*)d_in[0];
    float*       out = (float*)d_out;
    gmax_fused<<<B_DIM * SPLIT, 256>>>(in, out);
}

// round 12
// speedup vs baseline: 1.0068x; 1.0068x over previous
#include <cuda_runtime.h>
#include <math_constants.h>

// Global spatial max-pool: [B=64, H=56, W=56, C=256] f32 NHWC -> [B=64, C=256].
//
// R12: R7 config (best of 11 rounds: 35.0us kernel, 5.98 TB/s) with ONE
// change: ld.global.nc.L1::no_allocate.L2::256B -- ask L2 to fetch 256B per
// miss instead of default sector granularity. The 11-round evidence says the
// binding resource is the DRAM interface itself (~75% of spec across every
// SM-side configuration); coarser L2 fetches improve memory-controller burst
// coalescing and cannot over-fetch on this perfectly-sequential zero-reuse
// stream (every byte of every 256B fetch is demanded by adjacent requests).
// (Replaces evict_first, which measured <=+1%; the two qualifiers don't
// compose in one ld form.)
//
// Structure (unchanged from R7):
//   - grid = 64 batches x 28 splits = 1792 blocks, 256 threads
//     (32 channel-groups x 8 spatial phases); warp reads 1KB coalesced.
//   - compile-time trip count, immediate LDG offsets, unroll 4.
//   - smem cross-phase reduce; fused final reduce via last-block-per-batch
//     with release fence (write side) + acquire fence (read side) -- R6
//     proved the race is real without the acquire.
//   - counters self-reset for CUDA-graph replay determinism.

#define B_DIM   64
#define HW      3136              // 56*56
#define C_DIM   256
#define SPLIT   28
#define SPAN    (HW / SPLIT)      // 112 spatial positions per block
#define PHASES  8
#define ITERS   (SPAN / PHASES)   // 14

__device__ float        g_partial[B_DIM * SPLIT * C_DIM];  // 1.75 MB scratch
__device__ unsigned int g_count[B_DIM];                    // zero-init, self-resetting

__global__ __launch_bounds__(256, 8)
void gmax_fused(const float* __restrict__ in, float* __restrict__ out) {
    const int blk   = blockIdx.x;            // 0..1791
    const int b     = blk / SPLIT;
    const int split = blk - b * SPLIT;
    const int t     = threadIdx.x;
    const int g     = t & 31;                // 8-channel group (32 bytes)
    const int p     = t >> 5;                // spatial phase 0..7

    const float* __restrict__ base =
        in + (((size_t)(b * HW + split * SPAN + p)) << 8) + (g << 3);

    float a0 = -CUDART_INF_F, a1 = -CUDART_INF_F, a2 = -CUDART_INF_F, a3 = -CUDART_INF_F;
    float a4 = -CUDART_INF_F, a5 = -CUDART_INF_F, a6 = -CUDART_INF_F, a7 = -CUDART_INF_F;

    #pragma unroll 4
    for (int i = 0; i < ITERS; ++i) {
        float v0, v1, v2, v3, v4, v5, v6, v7;
        asm volatile(
            "ld.global.nc.L1::no_allocate.L2::256B.v8.f32 "
            "{%0,%1,%2,%3,%4,%5,%6,%7}, [%8];"
            : "=f"(v0), "=f"(v1), "=f"(v2), "=f"(v3),
              "=f"(v4), "=f"(v5), "=f"(v6), "=f"(v7)
            : "l"(base + (size_t)i * (PHASES * C_DIM)));
        a0 = fmaxf(a0, v0);  a1 = fmaxf(a1, v1);
        a2 = fmaxf(a2, v2);  a3 = fmaxf(a3, v3);
        a4 = fmaxf(a4, v4);  a5 = fmaxf(a5, v5);
        a6 = fmaxf(a6, v6);  a7 = fmaxf(a7, v7);
    }

    // Cross-phase reduce through smem: sm[p*256 + c], conflict-free.
    __shared__ float sm[PHASES * C_DIM];
    float* my = sm + t * 8;  // == p*256 + g*8
    my[0] = a0; my[1] = a1; my[2] = a2; my[3] = a3;
    my[4] = a4; my[5] = a5; my[6] = a6; my[7] = a7;
    __syncthreads();

    // Thread t == channel c: reduce over 8 phases, write block partial.
    {
        float m = sm[t];
        #pragma unroll
        for (int ph = 1; ph < PHASES; ++ph)
            m = fmaxf(m, sm[ph * C_DIM + t]);
        g_partial[blk * C_DIM + t] = m;
    }

    // Release: make partial visible, then bump the batch counter.
    __threadfence();
    __shared__ bool amLast;
    if (t == 0) {
        unsigned int old = atomicAdd(&g_count[b], 1u);
        amLast = (old == SPLIT - 1);
    }
    __syncthreads();

    if (amLast) {
        // Acquire: order our reads of g_partial after the observed counter.
        __threadfence();
        const float* part = g_partial + b * SPLIT * C_DIM;
        float m = part[t];
        #pragma unroll
        for (int s = 1; s < SPLIT; ++s)
            m = fmaxf(m, part[s * C_DIM + t]);
        out[b * C_DIM + t] = m;
        if (t == 0) g_count[b] = 0;   // self-reset for next graph replay
    }
}

extern "C" void kernel_launch(void* const* d_in, const int* in_sizes, int n_in,
                              void* d_out, int out_size) {
    const float* in  = (const float*)d_in[0];
    float*       out = (float*)d_out;
    gmax_fused<<<B_DIM * SPLIT, 256>>>(in, out);
}

// round 13
// speedup vs baseline: 1.0077x; 1.0009x over previous
#include <cuda_runtime.h>
#include <math_constants.h>

// Global spatial max-pool: [B=64, H=56, W=56, C=256] f32 NHWC -> [B=64, C=256].
//
// FINAL (12 rounds of measurement). This kernel sits on the chip's effective
// DRAM read ceiling: 5.87-5.98 TB/s (~74% of the 8 TB/s spec), 35.0-35.7us
// kernel time, bit-exact output.
//
// Evidence for the ceiling: every well-formed configuration tested --
// grid {896,1184,1792,2368,3584}, block {128,256,512}, occ 70-97%,
// MLP 2-28, epilogue {smem-reduce, none, persistent}, waves {0.76,1.0,1.51},
// cache {default, evict-first, L2::256B} -- lands at 5.8-6.0 TB/s.
// Regressions ruled out: in-loop barriers (-34%), runtime-bounded load
// loops (-13%), deep front-batch unroll (-3%).
//
// Structure:
//   - grid = 64 batches x 28 splits = 1792 blocks, 256 threads
//     (32 channel-groups x 8 spatial phases); warp reads 1KB coalesced.
//   - LDG.E.256 (ld.global.nc.v8.f32) + L1::no_allocate + L2::256B fetch:
//     zero-reuse stream, no L1 churn, full-line L2 fetches (cannot
//     over-fetch on a perfectly sequential stream).
//   - compile-time trip count, immediate LDG offsets, unroll 4 (best
//     measured steady-state MLP without front-batch L1tex-queue spread).
//   - smem cross-phase reduce; fused final reduce via last-block-per-batch:
//     release fence before the counter bump, acquire fence after observing
//     it (R6 measured rel_err 3e-4 without the acquire -- the race is real).
//   - counters self-reset for CUDA-graph replay determinism; max is
//     order-independent so block scheduling never affects output.

#define B_DIM   64
#define HW      3136              // 56*56
#define C_DIM   256
#define SPLIT   28
#define SPAN    (HW / SPLIT)      // 112 spatial positions per block
#define PHASES  8
#define ITERS   (SPAN / PHASES)   // 14

__device__ float        g_partial[B_DIM * SPLIT * C_DIM];  // 1.75 MB scratch
__device__ unsigned int g_count[B_DIM];                    // zero-init, self-resetting

__global__ __launch_bounds__(256, 8)
void gmax_fused(const float* __restrict__ in, float* __restrict__ out) {
    const int blk   = blockIdx.x;            // 0..1791
    const int b     = blk / SPLIT;
    const int split = blk - b * SPLIT;
    const int t     = threadIdx.x;
    const int g     = t & 31;                // 8-channel group (32 bytes)
    const int p     = t >> 5;                // spatial phase 0..7

    const float* __restrict__ base =
        in + (((size_t)(b * HW + split * SPAN + p)) << 8) + (g << 3);

    float a0 = -CUDART_INF_F, a1 = -CUDART_INF_F, a2 = -CUDART_INF_F, a3 = -CUDART_INF_F;
    float a4 = -CUDART_INF_F, a5 = -CUDART_INF_F, a6 = -CUDART_INF_F, a7 = -CUDART_INF_F;

    #pragma unroll 4
    for (int i = 0; i < ITERS; ++i) {
        float v0, v1, v2, v3, v4, v5, v6, v7;
        asm volatile(
            "ld.global.nc.L1::no_allocate.L2::256B.v8.f32 "
            "{%0,%1,%2,%3,%4,%5,%6,%7}, [%8];"
            : "=f"(v0), "=f"(v1), "=f"(v2), "=f"(v3),
              "=f"(v4), "=f"(v5), "=f"(v6), "=f"(v7)
            : "l"(base + (size_t)i * (PHASES * C_DIM)));
        a0 = fmaxf(a0, v0);  a1 = fmaxf(a1, v1);
        a2 = fmaxf(a2, v2);  a3 = fmaxf(a3, v3);
        a4 = fmaxf(a4, v4);  a5 = fmaxf(a5, v5);
        a6 = fmaxf(a6, v6);  a7 = fmaxf(a7, v7);
    }

    // Cross-phase reduce through smem: sm[p*256 + c], conflict-free.
    __shared__ float sm[PHASES * C_DIM];
    float* my = sm + t * 8;  // == p*256 + g*8
    my[0] = a0; my[1] = a1; my[2] = a2; my[3] = a3;
    my[4] = a4; my[5] = a5; my[6] = a6; my[7] = a7;
    __syncthreads();

    // Thread t == channel c: reduce over 8 phases, write block partial.
    {
        float m = sm[t];
        #pragma unroll
        for (int ph = 1; ph < PHASES; ++ph)
            m = fmaxf(m, sm[ph * C_DIM + t]);
        g_partial[blk * C_DIM + t] = m;
    }

    // Release: make partial visible, then bump the batch counter.
    __threadfence();
    __shared__ bool amLast;
    if (t == 0) {
        unsigned int old = atomicAdd(&g_count[b], 1u);
        amLast = (old == SPLIT - 1);
    }
    __syncthreads();

    if (amLast) {
        // Acquire: order our reads of g_partial after the observed counter.
        __threadfence();
        const float* part = g_partial + b * SPLIT * C_DIM;
        float m = part[t];
        #pragma unroll
        for (int s = 1; s < SPLIT; ++s)
            m = fmaxf(m, part[s * C_DIM + t]);
        out[b * C_DIM + t] = m;
        if (t == 0) g_count[b] = 0;   // self-reset for next graph replay
    }
}

extern "C" void kernel_launch(void* const* d_in, const int* in_sizes, int n_in,
                              void* d_out, int out_size) {
    const float* in  = (const float*)d_in[0];
    float*       out = (float*)d_out;
    gmax_fused<<<B_DIM * SPLIT, 256>>>(in, out);
}